// round 5
// baseline (speedup 1.0000x reference)
#include <cuda_runtime.h>

#define D 128
#define MAXN 50176        // padded node capacity (actual N = 50000)
#define MAXE 600000

// ---------------- scratch (no allocs allowed; referenced only in device code) ----------------
__device__ int   g_cnt[MAXN];          // in-degree counts
__device__ int   g_fill[MAXN];         // fill cursors for CSR build
__device__ int   g_row[MAXN + 1];      // CSR row offsets (by destination)
__device__ int   g_csrc[MAXE];         // CSR column = source node ids
__device__ float g_inv[MAXN];          // 1 / max(deg, 1)
__device__ float g_hop1[MAXN * D];
__device__ float g_hop2[MAXN * D];

// ---------------- zero the small int arrays ----------------
__global__ void zero_kernel() {
    int i = blockIdx.x * blockDim.x + threadIdx.x;
    if (i < MAXN) { g_cnt[i] = 0; g_fill[i] = 0; }
}

// ---------------- in-degree histogram ----------------
__global__ void degree_kernel(const int* __restrict__ ei, int E) {
    int e = blockIdx.x * blockDim.x + threadIdx.x;
    if (e < E) {
        int d = ei[E + e];             // destination row of edge_index
        atomicAdd(&g_cnt[d], 1);
    }
}

// ---------------- exclusive prefix sum over MAXN counts (single block) ----------------
__global__ void scan_kernel() {
    __shared__ int sh[1024];
    const int CH = MAXN / 1024;        // 49, exact
    int t = threadIdx.x;
    int base = t * CH;

    int s = 0;
    for (int i = 0; i < CH; i++) s += g_cnt[base + i];
    sh[t] = s;
    __syncthreads();

    // Hillis-Steele inclusive scan
    for (int off = 1; off < 1024; off <<= 1) {
        int v = (t >= off) ? sh[t - off] : 0;
        __syncthreads();
        sh[t] += v;
        __syncthreads();
    }

    int run = (t == 0) ? 0 : sh[t - 1];
    for (int i = 0; i < CH; i++) {
        int idx = base + i;
        int c = g_cnt[idx];
        g_row[idx] = run;
        g_inv[idx] = 1.0f / fmaxf((float)c, 1.0f);
        run += c;
    }
    if (t == 1023) g_row[MAXN] = run;
}

// ---------------- CSR fill ----------------
__global__ void fill_kernel(const int* __restrict__ ei, int E) {
    int e = blockIdx.x * blockDim.x + threadIdx.x;
    if (e < E) {
        int s = ei[e];
        int d = ei[E + e];
        int pos = g_row[d] + atomicAdd(&g_fill[d], 1);
        g_csrc[pos] = s;
    }
}

// ---------------- mean aggregation (pull): one warp per dst node ----------------
// pass 0: g_hop1 = mean_{src->n} x[src];   pass 1: g_hop2 = mean_{src->n} g_hop1[src]
__global__ void hop_kernel(const float* __restrict__ x, int pass, int n) {
    int w = (blockIdx.x * blockDim.x + threadIdx.x) >> 5;
    if (w >= n) return;
    int lane = threadIdx.x & 31;

    const float4* in = (pass == 0) ? (const float4*)x : (const float4*)g_hop1;
    float*        op = (pass == 0) ? g_hop1 : g_hop2;

    int beg = g_row[w];
    int end = g_row[w + 1];

    float ax = 0.f, ay = 0.f, az = 0.f, aw = 0.f;
    int j = beg;
    for (; j + 4 <= end; j += 4) {
        int s0 = __ldg(&g_csrc[j + 0]);
        int s1 = __ldg(&g_csrc[j + 1]);
        int s2 = __ldg(&g_csrc[j + 2]);
        int s3 = __ldg(&g_csrc[j + 3]);
        float4 v0 = __ldg(in + (size_t)s0 * 32 + lane);
        float4 v1 = __ldg(in + (size_t)s1 * 32 + lane);
        float4 v2 = __ldg(in + (size_t)s2 * 32 + lane);
        float4 v3 = __ldg(in + (size_t)s3 * 32 + lane);
        ax += v0.x; ay += v0.y; az += v0.z; aw += v0.w;
        ax += v1.x; ay += v1.y; az += v1.z; aw += v1.w;
        ax += v2.x; ay += v2.y; az += v2.z; aw += v2.w;
        ax += v3.x; ay += v3.y; az += v3.z; aw += v3.w;
    }
    for (; j < end; j++) {
        int s0 = __ldg(&g_csrc[j]);
        float4 v0 = __ldg(in + (size_t)s0 * 32 + lane);
        ax += v0.x; ay += v0.y; az += v0.z; aw += v0.w;
    }

    float inv = g_inv[w];
    float4 r = make_float4(ax * inv, ay * inv, az * inv, aw * inv);
    *((float4*)op + (size_t)w * 32 + lane) = r;
}

// ---------------- fused concat-GEMM: out = [x|hop1|hop2] @ W^T + b ----------------
// BM=128 nodes, BN=128 outputs, BK=32. 256 threads, 16x4 acc per thread.
__global__ __launch_bounds__(256, 2)
void gemm_kernel(const float* __restrict__ x,
                 const float* __restrict__ W,     // [128, 384] row-major
                 const float* __restrict__ bias,  // [128]
                 float* __restrict__ out, int n) {
    __shared__ float As[32][128];   // As[k][m]  (transposed feats tile)
    __shared__ float Bs[32][128];   // Bs[k][o]

    int tid  = threadIdx.x;
    int m0   = blockIdx.x * 128;
    int tcol = tid & 31;            // output group: o = tcol*4 .. +3
    int trow = tid >> 5;            // node group:   m = trow*16 .. +15

    float acc[16][4];
#pragma unroll
    for (int i = 0; i < 16; i++)
#pragma unroll
        for (int jj = 0; jj < 4; jj++) acc[i][jj] = 0.f;

    int l_k4 = (tid & 7) * 4;       // loader: k offset within tile
    int l_r  = tid >> 3;            // loader: row, +32 per pass

#pragma unroll 1
    for (int kt = 0; kt < 12; kt++) {
        int k0 = kt * 32;
        const float* A = (k0 < 128) ? x : (k0 < 256) ? g_hop1 : g_hop2;
        int ka = k0 & 127;

        __syncthreads();  // protect previous tile reads
#pragma unroll
        for (int p = 0; p < 4; p++) {
            int r = l_r + p * 32;
            int gn = m0 + r;
            float4 v = make_float4(0.f, 0.f, 0.f, 0.f);
            if (gn < n)
                v = __ldg((const float4*)(A + (size_t)gn * 128 + ka + l_k4));
            As[l_k4 + 0][r] = v.x;
            As[l_k4 + 1][r] = v.y;
            As[l_k4 + 2][r] = v.z;
            As[l_k4 + 3][r] = v.w;
            float4 wv = __ldg((const float4*)(W + (size_t)r * 384 + k0 + l_k4));
            Bs[l_k4 + 0][r] = wv.x;
            Bs[l_k4 + 1][r] = wv.y;
            Bs[l_k4 + 2][r] = wv.z;
            Bs[l_k4 + 3][r] = wv.w;
        }
        __syncthreads();

#pragma unroll
        for (int k = 0; k < 32; k++) {
            float4 b4 = *(const float4*)&Bs[k][tcol * 4];
            float4 a0 = *(const float4*)&As[k][trow * 16 + 0];
            float4 a1 = *(const float4*)&As[k][trow * 16 + 4];
            float4 a2 = *(const float4*)&As[k][trow * 16 + 8];
            float4 a3 = *(const float4*)&As[k][trow * 16 + 12];
            const float a[16] = {a0.x, a0.y, a0.z, a0.w,
                                 a1.x, a1.y, a1.z, a1.w,
                                 a2.x, a2.y, a2.z, a2.w,
                                 a3.x, a3.y, a3.z, a3.w};
#pragma unroll
            for (int i = 0; i < 16; i++) {
                acc[i][0] += a[i] * b4.x;
                acc[i][1] += a[i] * b4.y;
                acc[i][2] += a[i] * b4.z;
                acc[i][3] += a[i] * b4.w;
            }
        }
    }

    float4 bb = __ldg((const float4*)(bias + tcol * 4));
#pragma unroll
    for (int i = 0; i < 16; i++) {
        int gn = m0 + trow * 16 + i;
        if (gn < n) {
            float4 r = make_float4(acc[i][0] + bb.x, acc[i][1] + bb.y,
                                   acc[i][2] + bb.z, acc[i][3] + bb.w);
            *(float4*)(out + (size_t)gn * 128 + tcol * 4) = r;
        }
    }
}

// ---------------- launch ----------------
extern "C" void kernel_launch(void* const* d_in, const int* in_sizes, int n_in,
                              void* d_out, int out_size) {
    const float* x    = (const float*)d_in[0];
    const int*   ei   = (const int*)d_in[1];      // int32! (JAX x64 disabled)
    const float* W    = (const float*)d_in[2];
    const float* bias = (const float*)d_in[3];
    float*       out  = (float*)d_out;

    int n = in_sizes[0] / D;      // 50000
    int E = in_sizes[1] / 2;      // 600000

    // CSR build (by destination)
    zero_kernel<<<(MAXN + 255) / 256, 256>>>();
    degree_kernel<<<(E + 255) / 256, 256>>>(ei, E);
    scan_kernel<<<1, 1024>>>();
    fill_kernel<<<(E + 255) / 256, 256>>>(ei, E);

    // two mean-propagation hops (pull / gather, no float atomics)
    int hop_blocks = (n * 32 + 255) / 256;
    hop_kernel<<<hop_blocks, 256>>>(x, 0, n);
    hop_kernel<<<hop_blocks, 256>>>(x, 1, n);

    // fused concat + linear
    gemm_kernel<<<(n + 127) / 128, 256>>>(x, W, bias, out, n);
}